// round 11
// baseline (speedup 1.0000x reference)
#include <cuda_runtime.h>

#define T_STEPS 500
#define NB 4096
#define ROWS 14          // rows per CTA
#define HRR  7           // rows per half-warp in GEMM2
#define NCTA 296         // 2 CTAs per SM * 148
#define NTHR 128

typedef unsigned long long ull;

// packed fp32x2 FMA (sm_103a FFMA2)
__device__ __forceinline__ ull ffma2(ull a, ull b, ull c) {
    ull d;
    asm("fma.rn.f32x2 %0, %1, %2, %3;" : "=l"(d) : "l"(a), "l"(b), "l"(c));
    return d;
}
__device__ __forceinline__ float pair_sum(ull p) {
    return __uint_as_float((unsigned)p) + __uint_as_float((unsigned)(p >> 32));
}
__device__ __forceinline__ ull packf2(float lo, float hi) {
    return (ull)__float_as_uint(lo) | ((ull)__float_as_uint(hi) << 32);
}

// SMEM: w1pk[2][16][128] ull; floats hsm[2][14][132] (pad 132: paired rows
// r,r+7 differ by 924 = 28 mod 32 banks -> conflict-free), pp[2][2][14][48]
// (pad 48: 7*48 = 16 mod 32 -> disjoint half-warp banks), ys[14][32], b2s[64]
#define W1PK_U (2*16*128)     // 4096 ull = 32 KB
#define HS  132
#define PPS 48
#define HSM_F (2*ROWS*HS)     // 3696
#define PP_F  (2*2*ROWS*PPS)  // 2688
#define YS_F  (ROWS*32)       // 448
#define SMEM_BYTES (W1PK_U*8 + (HSM_F + PP_F + YS_F + 64)*4)  // 60352 B

__global__ __launch_bounds__(NTHR, 2)
void nsde7(const float* __restrict__ y0, const float* __restrict__ noise,
           const float* __restrict__ dw1, const float* __restrict__ db1,
           const float* __restrict__ dw2, const float* __restrict__ db2,
           const float* __restrict__ gw1, const float* __restrict__ gb1,
           const float* __restrict__ gw2, const float* __restrict__ gb2,
           float* __restrict__ out)
{
    extern __shared__ char smraw[];
    ull*   w1pk = (ull*)smraw;              // [m][kp][j]
    float* hsm  = (float*)(w1pk + W1PK_U);  // [m][r][HS]
    float* pp   = hsm + HSM_F;              // [m][jh][r][PPS]
    float* ys   = pp  + PP_F;               // [r][32]
    float* b2s  = ys  + YS_F;               // [2][32]

    const int tid  = threadIdx.x;
    const int lane = tid & 31;
    const int wid  = tid >> 5;
    const int m    = wid >> 1;              // 0 drift, 1 diffusion
    const int sub  = wid & 1;               // j-half for both GEMMs
    // overlapping base: floor(bid*4082/295); full coverage, duplicated rows
    // recompute identical values (deterministic duplicate writes)
    const int base = (int)(((long long)blockIdx.x * (NB - ROWS)) / (NCTA - 1));

    // GEMM1: lane owns hidden units j0, j1 over all 14 rows
    const int j0 = sub * 64 + lane;
    const int j1 = j0 + 32;
    // GEMM2: lane -> outputs il, il+16; half-warp -> 7-row half
    const int il    = lane & 15;
    const int rhalf = lane >> 4;

    // ---- stage W1 into SMEM as k-packed f32x2 ----
    for (int idx = tid; idx < W1PK_U; idx += NTHR) {
        int mm = idx >> 11, rest = idx & 2047;
        int kp = rest >> 7, j = rest & 127;
        const float* W = mm ? gw1 : dw1;
        w1pk[idx] = packf2(W[j * 32 + 2 * kp], W[j * 32 + 2 * kp + 1]);
    }
    // ---- W2 rows (i = il, il+16), j-half sub -> registers (64 ull) ----
    const float* W2 = m ? gw2 : dw2;
    ull w2p0[32], w2p1[32];
    #pragma unroll
    for (int t = 0; t < 16; t++) {
        double2 u0 = *(const double2*)(W2 + il * 128 + sub * 64 + t * 4);
        w2p0[2*t]   = __double_as_longlong(u0.x);
        w2p0[2*t+1] = __double_as_longlong(u0.y);
        double2 u1 = *(const double2*)(W2 + (il + 16) * 128 + sub * 64 + t * 4);
        w2p1[2*t]   = __double_as_longlong(u1.x);
        w2p1[2*t+1] = __double_as_longlong(u1.y);
    }
    const float* B1 = m ? gb1 : db1;
    const float b1_0 = B1[j0], b1_1 = B1[j1];
    if (tid < 64) b2s[tid] = (tid < 32) ? db2[tid] : gb2[tid - 32];

    // ---- init ys + out[0] (threads 0..111, one float4 each) ----
    if (tid < ROWS * 8) {
        int v4 = tid * 4;
        float4 val = *(const float4*)(y0 + (size_t)base * 32 + v4);
        *(float4*)(ys + v4) = val;
        *(float4*)(out + (size_t)base * 32 + v4) = val;
    }
    __syncthreads();

    const float dt   = 0.01f;
    const float sqdt = __fsqrt_rn(dt);
    const ull*   w1b = w1pk + m * 2048;
    float*       hwb = hsm + m * (ROWS * HS);
    const float* hrb = hsm + m * (ROWS * HS) + (rhalf * HRR) * HS + sub * 64;
    float*       ppb = pp + (m * 2 + sub) * (ROWS * PPS);

    for (int s = 0; s < T_STEPS; s++) {
        // prefetch step noise (consumed in update)
        float4 nv;
        if (tid < ROWS * 8)
            nv = *(const float4*)(noise + ((size_t)s * NB + base) * 32 + tid * 4);

        // ---- GEMM1: h[r][j0/j1] over all 14 rows; 1 y-load -> 4 ffma2 ----
        ull acc0[ROWS], acc1[ROWS];
        const ull bi0 = (ull)__float_as_uint(b1_0);
        const ull bi1 = (ull)__float_as_uint(b1_1);
        #pragma unroll
        for (int r = 0; r < ROWS; r++) { acc0[r] = bi0; acc1[r] = bi1; }
        #pragma unroll
        for (int k4 = 0; k4 < 8; k4++) {
            ull w00 = w1b[(2*k4)   * 128 + j0];
            ull w01 = w1b[(2*k4+1) * 128 + j0];
            ull w10 = w1b[(2*k4)   * 128 + j1];
            ull w11 = w1b[(2*k4+1) * 128 + j1];
            #pragma unroll
            for (int r = 0; r < ROWS; r++) {
                double2 yv = *(const double2*)(ys + r * 32 + k4 * 4);
                ull ylo = __double_as_longlong(yv.x);
                ull yhi = __double_as_longlong(yv.y);
                acc0[r] = ffma2(w00, ylo, acc0[r]);
                acc0[r] = ffma2(w01, yhi, acc0[r]);
                acc1[r] = ffma2(w10, ylo, acc1[r]);
                acc1[r] = ffma2(w11, yhi, acc1[r]);
            }
        }
        #pragma unroll
        for (int r = 0; r < ROWS; r++) {
            hwb[r * HS + j0] = fmaxf(pair_sum(acc0[r]), 0.0f);
            hwb[r * HS + j1] = fmaxf(pair_sum(acc1[r]), 0.0f);
        }
        // producer == consumer warp for this j-half: warp-level sync only
        __syncwarp();

        // ---- GEMM2: partials over own j-half; half-warps take 7-row halves ----
        ull a0[HRR], a1[HRR];
        #pragma unroll
        for (int r = 0; r < HRR; r++) { a0[r] = 0ull; a1[r] = 0ull; }
        #pragma unroll
        for (int j4 = 0; j4 < 16; j4++) {
            #pragma unroll
            for (int r = 0; r < HRR; r++) {
                double2 hv = *(const double2*)(hrb + r * HS + j4 * 4);
                ull hlo = __double_as_longlong(hv.x);
                ull hhi = __double_as_longlong(hv.y);
                a0[r] = ffma2(w2p0[2*j4],   hlo, a0[r]);
                a0[r] = ffma2(w2p0[2*j4+1], hhi, a0[r]);
                a1[r] = ffma2(w2p1[2*j4],   hlo, a1[r]);
                a1[r] = ffma2(w2p1[2*j4+1], hhi, a1[r]);
            }
        }
        #pragma unroll
        for (int r = 0; r < HRR; r++) {
            int row = rhalf * HRR + r;
            ppb[row * PPS + il]      = pair_sum(a0[r]);
            ppb[row * PPS + il + 16] = pair_sum(a1[r]);
        }
        __syncthreads();

        // ---- reduce halves + Euler–Maruyama: threads 0..111, float4 each ----
        if (tid < ROWS * 8) {
            int v4 = tid * 4;
            int r = v4 >> 5, i = v4 & 31;
            const float* p = pp + r * PPS + i;
            float4 pa = *(const float4*)(p);
            float4 pb = *(const float4*)(p + ROWS * PPS);
            float4 bv = *(const float4*)(b2s + i);
            float fx = pa.x + pb.x + bv.x;
            float fy = pa.y + pb.y + bv.y;
            float fz = pa.z + pb.z + bv.z;
            float fw = pa.w + pb.w + bv.w;
            const float* pg = p + 2 * ROWS * PPS;
            float4 ga = *(const float4*)(pg);
            float4 gb = *(const float4*)(pg + ROWS * PPS);
            float4 bg = *(const float4*)(b2s + 32 + i);
            float gx = ga.x + gb.x + bg.x;
            float gy = ga.y + gb.y + bg.y;
            float gz = ga.z + gb.z + bg.z;
            float gw = ga.w + gb.w + bg.w;
            float4 yv = *(const float4*)(ys + v4);
            float4 z;
            z.x = fmaf(gx, sqdt * nv.x, fmaf(fx, dt, yv.x));
            z.y = fmaf(gy, sqdt * nv.y, fmaf(fy, dt, yv.y));
            z.z = fmaf(gz, sqdt * nv.z, fmaf(fz, dt, yv.z));
            z.w = fmaf(gw, sqdt * nv.w, fmaf(fw, dt, yv.w));
            *(float4*)(out + ((size_t)(s + 1) * NB + base) * 32 + v4) = z;
            *(float4*)(ys + v4) = z;   // rewrites exactly what it read
        }
        __syncthreads();
    }
}

extern "C" void kernel_launch(void* const* d_in, const int* in_sizes, int n_in,
                              void* d_out, int out_size)
{
    // metadata order: ts, y0, noise, drift_w1, drift_b1, drift_w2, drift_b2,
    //                 diff_w1, diff_b1, diff_w2, diff_b2
    const float* y0    = (const float*)d_in[1];
    const float* noise = (const float*)d_in[2];
    const float* dw1   = (const float*)d_in[3];
    const float* db1   = (const float*)d_in[4];
    const float* dw2   = (const float*)d_in[5];
    const float* db2   = (const float*)d_in[6];
    const float* gw1   = (const float*)d_in[7];
    const float* gb1   = (const float*)d_in[8];
    const float* gw2   = (const float*)d_in[9];
    const float* gb2   = (const float*)d_in[10];
    float* out = (float*)d_out;

    cudaFuncSetAttribute(nsde7,
                         cudaFuncAttributeMaxDynamicSharedMemorySize,
                         SMEM_BYTES);
    nsde7<<<NCTA, NTHR, SMEM_BYTES>>>(y0, noise, dw1, db1, dw2, db2,
                                      gw1, gb1, gw2, gb2, out);
}

// round 12
// speedup vs baseline: 1.0452x; 1.0452x over previous
#include <cuda_runtime.h>

#define T_STEPS 500
#define NB 4096
#define ROWS 28          // rows per CTA (with overlap; 148*28 >= 4096)
#define HR   14          // half rows
#define NCTA 148
#define NTHR 256

typedef unsigned long long ull;

// packed fp32x2 FMA (sm_103a FFMA2)
__device__ __forceinline__ ull ffma2(ull a, ull b, ull c) {
    ull d;
    asm("fma.rn.f32x2 %0, %1, %2, %3;" : "=l"(d) : "l"(a), "l"(b), "l"(c));
    return d;
}
__device__ __forceinline__ float pair_sum(ull p) {
    return __uint_as_float((unsigned)p) + __uint_as_float((unsigned)(p >> 32));
}
__device__ __forceinline__ ull packf2(float lo, float hi) {
    return (ull)__float_as_uint(lo) | ((ull)__float_as_uint(hi) << 32);
}

// SMEM: w1pk[2][16][128] ull; floats hsm[2][28][132], pp[2][4][28][40],
// ys[28][32], b2s[64].
//   hsm stride 132: half-warp row offset 14*132 = 1848 = 24 mod 32 banks ->
//     upper half-warp double2 hits banks +24/+25, disjoint from lower pair.
//   pp stride 40: 14*40 = 560 = 16 mod 32 -> upper half-warp stores land on
//     banks il+16, disjoint from lower il. All GEMM2 accesses single-phase.
#define W1PK_U (2*16*128)                 // 4096 ull = 32 KB
#define HS   132
#define PPS  40
#define HSM_F  (2*ROWS*HS)                // 7392
#define PP_F   (2*4*ROWS*PPS)             // 8960
#define YS_F   (ROWS*32)                  // 896
#define SMEM_BYTES (W1PK_U*8 + (HSM_F + PP_F + YS_F + 64)*4)  // 102,016 B

__global__ __launch_bounds__(NTHR, 1)
void nsde8(const float* __restrict__ y0, const float* __restrict__ noise,
           const float* __restrict__ dw1, const float* __restrict__ db1,
           const float* __restrict__ dw2, const float* __restrict__ db2,
           const float* __restrict__ gw1, const float* __restrict__ gb1,
           const float* __restrict__ gw2, const float* __restrict__ gb2,
           float* __restrict__ out)
{
    extern __shared__ char smraw[];
    ull*   w1pk = (ull*)smraw;              // [m][kp][j]
    float* hsm  = (float*)(w1pk + W1PK_U);  // [m][r][HS]
    float* pp   = hsm + HSM_F;              // [m][q][r][PPS]
    float* ys   = pp  + PP_F;               // [r][32]
    float* b2s  = ys  + YS_F;               // [2][32]

    const int tid  = threadIdx.x;
    const int lane = tid & 31;
    const int wid  = tid >> 5;
    const int m    = wid >> 2;              // 0 drift, 1 diffusion
    // overlapping base: floor(bid*4068/147); coverage has no gaps, dup rows
    // are recomputed identically (deterministic duplicate writes)
    const int base = (int)(((long long)blockIdx.x * (NB - ROWS)) / (NCTA - 1));

    // GEMM1 role: j-half + r-half
    const int hj  = (wid >> 1) & 1;
    const int rb1 = (wid & 1) * HR;
    const int j0  = hj * 64 + lane;
    const int j1  = j0 + 32;

    // GEMM2 role: j-quarter; lane -> outputs il, il+16; half-warp -> r-half
    const int q   = wid & 3;
    const int il  = lane & 15;
    const int rb2 = (lane >> 4) * HR;

    // ---- stage W1 into SMEM as k-packed f32x2 ----
    for (int idx = tid; idx < W1PK_U; idx += NTHR) {
        int mm = idx >> 11, rest = idx & 2047;
        int kp = rest >> 7, j = rest & 127;
        const float* W = mm ? gw1 : dw1;
        w1pk[idx] = packf2(W[j * 32 + 2 * kp], W[j * 32 + 2 * kp + 1]);
    }
    // ---- W2 rows (i = il, il+16) for this quarter -> registers ----
    const float* W2 = m ? gw2 : dw2;
    ull w2p0[16], w2p1[16];
    #pragma unroll
    for (int t = 0; t < 8; t++) {
        double2 u0 = *(const double2*)(W2 + il * 128 + q * 32 + t * 4);
        w2p0[2*t]   = __double_as_longlong(u0.x);
        w2p0[2*t+1] = __double_as_longlong(u0.y);
        double2 u1 = *(const double2*)(W2 + (il + 16) * 128 + q * 32 + t * 4);
        w2p1[2*t]   = __double_as_longlong(u1.x);
        w2p1[2*t+1] = __double_as_longlong(u1.y);
    }
    const float* B1 = m ? gb1 : db1;
    const float b1_0 = B1[j0], b1_1 = B1[j1];
    if (tid < 64) b2s[tid] = (tid < 32) ? db2[tid] : gb2[tid - 32];

    // ---- init ys + out[0] (threads 0..223, one float4 each) ----
    if (tid < ROWS * 8) {
        int v4 = tid * 4;
        float4 val = *(const float4*)(y0 + (size_t)base * 32 + v4);
        *(float4*)(ys + v4) = val;
        *(float4*)(out + (size_t)base * 32 + v4) = val;
    }
    __syncthreads();

    const float dt   = 0.01f;
    const float sqdt = __fsqrt_rn(dt);
    const ull*   w1b = w1pk + m * 2048;
    float*       hwb = hsm + m * (ROWS * HS);
    const float* hq  = hsm + m * (ROWS * HS) + q * 32;
    float*       ppb = pp + (m * 4 + q) * (ROWS * PPS);

    for (int s = 0; s < T_STEPS; s++) {
        // prefetch step noise (float4, threads 0..223)
        float4 nv;
        if (tid < ROWS * 8)
            nv = *(const float4*)(noise + ((size_t)s * NB + base) * 32 + tid * 4);

        // ---- GEMM1: h[r][j0/j1] over HR rows; 1 y-load -> 4 ffma2 ----
        ull acc0[HR], acc1[HR];
        const ull bi0 = (ull)__float_as_uint(b1_0);
        const ull bi1 = (ull)__float_as_uint(b1_1);
        #pragma unroll
        for (int r = 0; r < HR; r++) { acc0[r] = bi0; acc1[r] = bi1; }
        #pragma unroll
        for (int k4 = 0; k4 < 8; k4++) {
            ull w00 = w1b[(2*k4)   * 128 + j0];
            ull w01 = w1b[(2*k4+1) * 128 + j0];
            ull w10 = w1b[(2*k4)   * 128 + j1];
            ull w11 = w1b[(2*k4+1) * 128 + j1];
            #pragma unroll
            for (int r = 0; r < HR; r++) {
                double2 yv = *(const double2*)(ys + (rb1 + r) * 32 + k4 * 4);
                ull ylo = __double_as_longlong(yv.x);
                ull yhi = __double_as_longlong(yv.y);
                acc0[r] = ffma2(w00, ylo, acc0[r]);
                acc0[r] = ffma2(w01, yhi, acc0[r]);
                acc1[r] = ffma2(w10, ylo, acc1[r]);
                acc1[r] = ffma2(w11, yhi, acc1[r]);
            }
        }
        #pragma unroll
        for (int r = 0; r < HR; r++) {
            hwb[(rb1 + r) * HS + j0] = fmaxf(pair_sum(acc0[r]), 0.0f);
            hwb[(rb1 + r) * HS + j1] = fmaxf(pair_sum(acc1[r]), 0.0f);
        }
        __syncthreads();

        // ---- GEMM2: partial[r][il/il+16] over HR rows; 1 h-load -> 4 ffma2 ----
        ull a0[HR], a1[HR];
        #pragma unroll
        for (int r = 0; r < HR; r++) { a0[r] = 0ull; a1[r] = 0ull; }
        #pragma unroll
        for (int j4 = 0; j4 < 8; j4++) {
            #pragma unroll
            for (int r = 0; r < HR; r++) {
                double2 hv = *(const double2*)(hq + (rb2 + r) * HS + j4 * 4);
                ull hlo = __double_as_longlong(hv.x);
                ull hhi = __double_as_longlong(hv.y);
                a0[r] = ffma2(w2p0[2*j4],   hlo, a0[r]);
                a0[r] = ffma2(w2p0[2*j4+1], hhi, a0[r]);
                a1[r] = ffma2(w2p1[2*j4],   hlo, a1[r]);
                a1[r] = ffma2(w2p1[2*j4+1], hhi, a1[r]);
            }
        }
        #pragma unroll
        for (int r = 0; r < HR; r++) {
            ppb[(rb2 + r) * PPS + il]      = pair_sum(a0[r]);
            ppb[(rb2 + r) * PPS + il + 16] = pair_sum(a1[r]);
        }
        __syncthreads();

        // ---- reduce quarters + Euler–Maruyama: threads 0..223, float4 each ----
        if (tid < ROWS * 8) {
            int v4 = tid * 4;
            int r = v4 >> 5, i = v4 & 31;
            const float* p = pp + r * PPS + i;
            float4 pa = *(const float4*)(p);
            float4 pb = *(const float4*)(p + ROWS*PPS);
            float4 pc = *(const float4*)(p + 2*ROWS*PPS);
            float4 pd = *(const float4*)(p + 3*ROWS*PPS);
            float4 bv = *(const float4*)(b2s + i);
            float fx = pa.x + pb.x + pc.x + pd.x + bv.x;
            float fy = pa.y + pb.y + pc.y + pd.y + bv.y;
            float fz = pa.z + pb.z + pc.z + pd.z + bv.z;
            float fw = pa.w + pb.w + pc.w + pd.w + bv.w;
            const float* pg = p + 4*ROWS*PPS;
            float4 ga = *(const float4*)(pg);
            float4 gb = *(const float4*)(pg + ROWS*PPS);
            float4 gc = *(const float4*)(pg + 2*ROWS*PPS);
            float4 gd = *(const float4*)(pg + 3*ROWS*PPS);
            float4 bg = *(const float4*)(b2s + 32 + i);
            float gx = ga.x + gb.x + gc.x + gd.x + bg.x;
            float gy = ga.y + gb.y + gc.y + gd.y + bg.y;
            float gz = ga.z + gb.z + gc.z + gd.z + bg.z;
            float gw = ga.w + gb.w + gc.w + gd.w + bg.w;
            float4 yv = *(const float4*)(ys + v4);
            float4 z;
            z.x = fmaf(gx, sqdt * nv.x, fmaf(fx, dt, yv.x));
            z.y = fmaf(gy, sqdt * nv.y, fmaf(fy, dt, yv.y));
            z.z = fmaf(gz, sqdt * nv.z, fmaf(fz, dt, yv.z));
            z.w = fmaf(gw, sqdt * nv.w, fmaf(fw, dt, yv.w));
            *(float4*)(out + ((size_t)(s + 1) * NB + base) * 32 + v4) = z;
            *(float4*)(ys + v4) = z;   // rewrites exactly what it read
        }
        __syncthreads();
    }
}

extern "C" void kernel_launch(void* const* d_in, const int* in_sizes, int n_in,
                              void* d_out, int out_size)
{
    // metadata order: ts, y0, noise, drift_w1, drift_b1, drift_w2, drift_b2,
    //                 diff_w1, diff_b1, diff_w2, diff_b2
    const float* y0    = (const float*)d_in[1];
    const float* noise = (const float*)d_in[2];
    const float* dw1   = (const float*)d_in[3];
    const float* db1   = (const float*)d_in[4];
    const float* dw2   = (const float*)d_in[5];
    const float* db2   = (const float*)d_in[6];
    const float* gw1   = (const float*)d_in[7];
    const float* gb1   = (const float*)d_in[8];
    const float* gw2   = (const float*)d_in[9];
    const float* gb2   = (const float*)d_in[10];
    float* out = (float*)d_out;

    cudaFuncSetAttribute(nsde8,
                         cudaFuncAttributeMaxDynamicSharedMemorySize,
                         SMEM_BYTES);
    nsde8<<<NCTA, NTHR, SMEM_BYTES>>>(y0, noise, dw1, db1, dw2, db2,
                                      gw1, gb1, gw2, gb2, out);
}

// round 13
// speedup vs baseline: 1.0591x; 1.0133x over previous
#include <cuda_runtime.h>

#define T_STEPS 500
#define NB 4096
#define ROWS 28          // rows per CTA (with overlap; 148*28 >= 4096)
#define HR   14          // half rows
#define NCTA 148
#define NTHR 256

typedef unsigned long long ull;

// packed fp32x2 FMA (sm_103a FFMA2)
__device__ __forceinline__ ull ffma2(ull a, ull b, ull c) {
    ull d;
    asm("fma.rn.f32x2 %0, %1, %2, %3;" : "=l"(d) : "l"(a), "l"(b), "l"(c));
    return d;
}
__device__ __forceinline__ float pair_sum(ull p) {
    return __uint_as_float((unsigned)p) + __uint_as_float((unsigned)(p >> 32));
}
__device__ __forceinline__ ull packf2(float lo, float hi) {
    return (ull)__float_as_uint(lo) | ((ull)__float_as_uint(hi) << 32);
}
// named barrier: drift group (tids 0-127) id=1, diffusion group id=2
__device__ __forceinline__ void bar_group(int id) {
    asm volatile("bar.sync %0, %1;" :: "r"(id), "r"(128) : "memory");
}

// SMEM: w1pk[2][16][128] ull; floats hsm[2][28][132], pp[2][4][28][40],
// ys[28][32], b2s[64].  (padding rationale: see R12 — all GEMM2 accesses
// single-phase)
#define W1PK_U (2*16*128)                 // 4096 ull = 32 KB
#define HS   132
#define PPS  40
#define HSM_F  (2*ROWS*HS)                // 7392
#define PP_F   (2*4*ROWS*PPS)             // 8960
#define YS_F   (ROWS*32)                  // 896
#define SMEM_BYTES (W1PK_U*8 + (HSM_F + PP_F + YS_F + 64)*4)  // 102,016 B

__global__ __launch_bounds__(NTHR, 1)
void nsde9(const float* __restrict__ y0, const float* __restrict__ noise,
           const float* __restrict__ dw1, const float* __restrict__ db1,
           const float* __restrict__ dw2, const float* __restrict__ db2,
           const float* __restrict__ gw1, const float* __restrict__ gb1,
           const float* __restrict__ gw2, const float* __restrict__ gb2,
           float* __restrict__ out)
{
    extern __shared__ char smraw[];
    ull*   w1pk = (ull*)smraw;              // [m][kp][j]
    float* hsm  = (float*)(w1pk + W1PK_U);  // [m][r][HS]
    float* pp   = hsm + HSM_F;              // [m][q][r][PPS]
    float* ys   = pp  + PP_F;               // [r][32]
    float* b2s  = ys  + YS_F;               // [2][32]

    const int tid  = threadIdx.x;
    const int lane = tid & 31;
    const int wid  = tid >> 5;
    const int m    = wid >> 2;              // 0 drift, 1 diffusion
    // overlapping base: floor(bid*4068/147); coverage has no gaps, dup rows
    // are recomputed identically (deterministic duplicate writes)
    const int base = (int)(((long long)blockIdx.x * (NB - ROWS)) / (NCTA - 1));

    // GEMM1 role: j-half + r-half
    const int hj  = (wid >> 1) & 1;
    const int rb1 = (wid & 1) * HR;
    const int j0  = hj * 64 + lane;
    const int j1  = j0 + 32;

    // GEMM2 role: j-quarter; lane -> outputs il, il+16; half-warp -> r-half
    const int q   = wid & 3;
    const int il  = lane & 15;
    const int rb2 = (lane >> 4) * HR;

    // ---- stage W1 into SMEM as k-packed f32x2 ----
    for (int idx = tid; idx < W1PK_U; idx += NTHR) {
        int mm = idx >> 11, rest = idx & 2047;
        int kp = rest >> 7, j = rest & 127;
        const float* W = mm ? gw1 : dw1;
        w1pk[idx] = packf2(W[j * 32 + 2 * kp], W[j * 32 + 2 * kp + 1]);
    }
    // ---- W2 rows (i = il, il+16) for this quarter -> registers ----
    const float* W2 = m ? gw2 : dw2;
    ull w2p0[16], w2p1[16];
    #pragma unroll
    for (int t = 0; t < 8; t++) {
        double2 u0 = *(const double2*)(W2 + il * 128 + q * 32 + t * 4);
        w2p0[2*t]   = __double_as_longlong(u0.x);
        w2p0[2*t+1] = __double_as_longlong(u0.y);
        double2 u1 = *(const double2*)(W2 + (il + 16) * 128 + q * 32 + t * 4);
        w2p1[2*t]   = __double_as_longlong(u1.x);
        w2p1[2*t+1] = __double_as_longlong(u1.y);
    }
    const float* B1 = m ? gb1 : db1;
    const float b1_0 = B1[j0], b1_1 = B1[j1];
    if (tid < 64) b2s[tid] = (tid < 32) ? db2[tid] : gb2[tid - 32];

    // ---- init ys + out[0] (threads 0..223, one float4 each) ----
    if (tid < ROWS * 8) {
        int v4 = tid * 4;
        float4 val = *(const float4*)(y0 + (size_t)base * 32 + v4);
        *(float4*)(ys + v4) = val;
        *(float4*)(out + (size_t)base * 32 + v4) = val;
    }
    __syncthreads();

    const float dt   = 0.01f;
    const float sqdt = __fsqrt_rn(dt);
    const ull*   w1b = w1pk + m * 2048;
    float*       hwb = hsm + m * (ROWS * HS);
    const float* hq  = hsm + m * (ROWS * HS) + q * 32;
    float*       ppb = pp + (m * 4 + q) * (ROWS * PPS);

    // k4=0 weights are loop-invariant: load once (kills the post-barrier
    // LDS-latency bubble at the top of every GEMM1)
    const ull wA0 = w1b[0 * 128 + j0];
    const ull wA1 = w1b[1 * 128 + j0];
    const ull wB0 = w1b[0 * 128 + j1];
    const ull wB1 = w1b[1 * 128 + j1];

    for (int s = 0; s < T_STEPS; s++) {
        // prefetch step noise (float4, threads 0..223)
        float4 nv;
        if (tid < ROWS * 8)
            nv = *(const float4*)(noise + ((size_t)s * NB + base) * 32 + tid * 4);

        // ---- GEMM1: h[r][j0/j1] over HR rows; 1 y-load -> 4 ffma2 ----
        ull acc0[HR], acc1[HR];
        // k4 = 0 with preloaded weights (bias folded into init)
        #pragma unroll
        for (int r = 0; r < HR; r++) {
            double2 yv = *(const double2*)(ys + (rb1 + r) * 32);
            ull ylo = __double_as_longlong(yv.x);
            ull yhi = __double_as_longlong(yv.y);
            ull a = ffma2(wA0, ylo, (ull)__float_as_uint(b1_0));
            a = ffma2(wA1, yhi, a);
            ull b = ffma2(wB0, ylo, (ull)__float_as_uint(b1_1));
            b = ffma2(wB1, yhi, b);
            acc0[r] = a; acc1[r] = b;
        }
        #pragma unroll
        for (int k4 = 1; k4 < 8; k4++) {
            ull w00 = w1b[(2*k4)   * 128 + j0];
            ull w01 = w1b[(2*k4+1) * 128 + j0];
            ull w10 = w1b[(2*k4)   * 128 + j1];
            ull w11 = w1b[(2*k4+1) * 128 + j1];
            #pragma unroll
            for (int r = 0; r < HR; r++) {
                double2 yv = *(const double2*)(ys + (rb1 + r) * 32 + k4 * 4);
                ull ylo = __double_as_longlong(yv.x);
                ull yhi = __double_as_longlong(yv.y);
                acc0[r] = ffma2(w00, ylo, acc0[r]);
                acc0[r] = ffma2(w01, yhi, acc0[r]);
                acc1[r] = ffma2(w10, ylo, acc1[r]);
                acc1[r] = ffma2(w11, yhi, acc1[r]);
            }
        }
        #pragma unroll
        for (int r = 0; r < HR; r++) {
            hwb[(rb1 + r) * HS + j0] = fmaxf(pair_sum(acc0[r]), 0.0f);
            hwb[(rb1 + r) * HS + j1] = fmaxf(pair_sum(acc1[r]), 0.0f);
        }
        // h[m] produced and consumed entirely within group m: group barrier
        // only — lets drift/diffusion groups run out of phase
        bar_group(1 + m);

        // ---- GEMM2: partial[r][il/il+16] over HR rows; 1 h-load -> 4 ffma2 ----
        ull a0[HR], a1[HR];
        #pragma unroll
        for (int r = 0; r < HR; r++) { a0[r] = 0ull; a1[r] = 0ull; }
        #pragma unroll
        for (int j4 = 0; j4 < 8; j4++) {
            #pragma unroll
            for (int r = 0; r < HR; r++) {
                double2 hv = *(const double2*)(hq + (rb2 + r) * HS + j4 * 4);
                ull hlo = __double_as_longlong(hv.x);
                ull hhi = __double_as_longlong(hv.y);
                a0[r] = ffma2(w2p0[2*j4],   hlo, a0[r]);
                a0[r] = ffma2(w2p0[2*j4+1], hhi, a0[r]);
                a1[r] = ffma2(w2p1[2*j4],   hlo, a1[r]);
                a1[r] = ffma2(w2p1[2*j4+1], hhi, a1[r]);
            }
        }
        #pragma unroll
        for (int r = 0; r < HR; r++) {
            ppb[(rb2 + r) * PPS + il]      = pair_sum(a0[r]);
            ppb[(rb2 + r) * PPS + il + 16] = pair_sum(a1[r]);
        }
        __syncthreads();

        // ---- reduce quarters + Euler–Maruyama: threads 0..223, float4 each ----
        if (tid < ROWS * 8) {
            int v4 = tid * 4;
            int r = v4 >> 5, i = v4 & 31;
            const float* p = pp + r * PPS + i;
            float4 pa = *(const float4*)(p);
            float4 pb = *(const float4*)(p + ROWS*PPS);
            float4 pc = *(const float4*)(p + 2*ROWS*PPS);
            float4 pd = *(const float4*)(p + 3*ROWS*PPS);
            float4 bv = *(const float4*)(b2s + i);
            float fx = pa.x + pb.x + pc.x + pd.x + bv.x;
            float fy = pa.y + pb.y + pc.y + pd.y + bv.y;
            float fz = pa.z + pb.z + pc.z + pd.z + bv.z;
            float fw = pa.w + pb.w + pc.w + pd.w + bv.w;
            const float* pg = p + 4*ROWS*PPS;
            float4 ga = *(const float4*)(pg);
            float4 gb = *(const float4*)(pg + ROWS*PPS);
            float4 gc = *(const float4*)(pg + 2*ROWS*PPS);
            float4 gd = *(const float4*)(pg + 3*ROWS*PPS);
            float4 bg = *(const float4*)(b2s + 32 + i);
            float gx = ga.x + gb.x + gc.x + gd.x + bg.x;
            float gy = ga.y + gb.y + gc.y + gd.y + bg.y;
            float gz = ga.z + gb.z + gc.z + gd.z + bg.z;
            float gw = ga.w + gb.w + gc.w + gd.w + bg.w;
            float4 yv = *(const float4*)(ys + v4);
            float4 z;
            z.x = fmaf(gx, sqdt * nv.x, fmaf(fx, dt, yv.x));
            z.y = fmaf(gy, sqdt * nv.y, fmaf(fy, dt, yv.y));
            z.z = fmaf(gz, sqdt * nv.z, fmaf(fz, dt, yv.z));
            z.w = fmaf(gw, sqdt * nv.w, fmaf(fw, dt, yv.w));
            *(float4*)(out + ((size_t)(s + 1) * NB + base) * 32 + v4) = z;
            *(float4*)(ys + v4) = z;   // rewrites exactly what it read
        }
        __syncthreads();
    }
}

extern "C" void kernel_launch(void* const* d_in, const int* in_sizes, int n_in,
                              void* d_out, int out_size)
{
    // metadata order: ts, y0, noise, drift_w1, drift_b1, drift_w2, drift_b2,
    //                 diff_w1, diff_b1, diff_w2, diff_b2
    const float* y0    = (const float*)d_in[1];
    const float* noise = (const float*)d_in[2];
    const float* dw1   = (const float*)d_in[3];
    const float* db1   = (const float*)d_in[4];
    const float* dw2   = (const float*)d_in[5];
    const float* db2   = (const float*)d_in[6];
    const float* gw1   = (const float*)d_in[7];
    const float* gb1   = (const float*)d_in[8];
    const float* gw2   = (const float*)d_in[9];
    const float* gb2   = (const float*)d_in[10];
    float* out = (float*)d_out;

    cudaFuncSetAttribute(nsde9,
                         cudaFuncAttributeMaxDynamicSharedMemorySize,
                         SMEM_BYTES);
    nsde9<<<NCTA, NTHR, SMEM_BYTES>>>(y0, noise, dw1, db1, dw2, db2,
                                      gw1, gb1, gw2, gb2, out);
}